// round 9
// baseline (speedup 1.0000x reference)
#include <cuda_runtime.h>
#include <cuda_bf16.h>
#include <cstdint>

// Problem constants (fixed by the dataset)
#define NN   20000
#define EE   160000
#define HID  128
#define NHEADS 4
#define GG   64
#define NCC  8
#define HC   512
#define MPK  2560      // packed projection width: [skip | q | k | v | ts]
#define NEGBIG (-1.0e30f)

// ---------------------------------------------------------------------------
// Scratch (device globals: allocation-free contract)
// ---------------------------------------------------------------------------
__device__ float g_agg [NN * HID];
__device__ float g_h   [NN * HID];
__device__ float g_h3  [NN * HID];
__device__ float g_h4  [NN * HID];
__device__ float g_h5  [NN * HID];
__device__ float g_pack[(size_t)NN * MPK];
__device__ float g_h2  [NN * HC];
__device__ float g_Wpk [HID * MPK];
__device__ float g_bpk [MPK];
__device__ float g_pool[GG * HID];
__device__ float g_cnt [GG];
// CSR (by dst)
__device__ int   g_deg [NN];
__device__ int   g_cur [NN];
__device__ int   g_off [NN + 1];
__device__ int   g_srcs[EE];

// ---------------------------------------------------------------------------
// mma.sync bf16 GEMM, 3xBF16 split, cp.async double-buffered fp32 staging.
// C[Nrows, Mtot] = op( A@W [+ A2@W2] [+bias] [+add1] ), W: [K, Mtot]
// CTA tile 128x64, BK=32. 8 warps (2m x 4n), warp tile 64x16, 2 CTAs/SM.
//
// Dynamic smem layout (bytes):
//   [0,18432)        A stage 0 (fp32, 128 rows x 144B padded)
//   [18432,36864)    A stage 1
//   [36864,45056)    B stage 0 (fp32, 32 k-rows x 256B)
//   [45056,53248)    B stage 1
//   [53248,+30720)   bf16 hi/lo tiles (SSTR=80B rows)
// ---------------------------------------------------------------------------
#define STG_A0 0
#define STG_A1 18432
#define STG_B0 36864
#define STG_B1 45056
#define TILEB  53248
#define A_HI (TILEB + 0)
#define A_LO (TILEB + 10240)
#define B_HI (TILEB + 20480)
#define B_LO (TILEB + 25600)
#define GEMM_SMEM (TILEB + 30720)   // 83968
#define SSTR 80
#define ASTR 144   // padded fp32 A-stage row stride (bytes)

__device__ __forceinline__ unsigned pack_hi(float x, float y) {
    __nv_bfloat162 p;
    p.x = __float2bfloat16_rn(x);
    p.y = __float2bfloat16_rn(y);
    return *(unsigned*)&p;
}
__device__ __forceinline__ unsigned pack_lo(float x, float y) {
    __nv_bfloat162 p;
    p.x = __float2bfloat16_rn(x - __bfloat162float(__float2bfloat16_rn(x)));
    p.y = __float2bfloat16_rn(y - __bfloat162float(__float2bfloat16_rn(y)));
    return *(unsigned*)&p;
}

__device__ __forceinline__ void mma_bf16(float* c, const unsigned* a, const unsigned* b) {
    asm volatile(
        "mma.sync.aligned.m16n8k16.row.col.f32.bf16.bf16.f32 "
        "{%0,%1,%2,%3}, {%4,%5,%6,%7}, {%8,%9}, {%0,%1,%2,%3};"
        : "+f"(c[0]), "+f"(c[1]), "+f"(c[2]), "+f"(c[3])
        : "r"(a[0]), "r"(a[1]), "r"(a[2]), "r"(a[3]), "r"(b[0]), "r"(b[1]));
}

__device__ __forceinline__ uint32_t smem_u32(const void* p) {
    uint32_t a;
    asm("{ .reg .u64 t; cvta.to.shared.u64 t, %1; cvt.u32.u64 %0, t; }"
        : "=r"(a) : "l"(p));
    return a;
}

// Issue one chunk's global->shared async copies (A: 4/thread, B: 2/thread)
__device__ __forceinline__ void issue_tiles(const float* __restrict__ Ap,
                                            const float* __restrict__ Wp,
                                            int K, int Mtot, int Nrows,
                                            int brow, int bcol, int k0, int tid,
                                            uint32_t stgA, uint32_t stgB)
{
#pragma unroll
    for (int t = 0; t < 4; ++t) {
        int idx = tid + t * 256;          // 0..1023
        int r   = idx >> 3;               // 0..127
        int kg  = idx & 7;                // 0..7
        uint32_t dst = stgA + r * ASTR + kg * 16;
        const float* src = Ap + (size_t)(brow + r) * K + k0 + kg * 4;
        int bytes = (brow + r < Nrows) ? 16 : 0;   // OOB rows -> zero-fill
        asm volatile("cp.async.cg.shared.global [%0], [%1], 16, %2;"
            :: "r"(dst), "l"(src), "r"(bytes));
    }
#pragma unroll
    for (int t = 0; t < 2; ++t) {
        int idx = tid + t * 256;          // 0..511
        int krow = idx >> 4;              // 0..31
        int cg   = idx & 15;              // 0..15 (float4 within 64-col row)
        uint32_t dst = stgB + krow * 256 + cg * 16;
        const float* src = Wp + (size_t)(k0 + krow) * Mtot + bcol + cg * 4;
        asm volatile("cp.async.cg.shared.global [%0], [%1], 16;"
            :: "r"(dst), "l"(src));
    }
}

__global__ void __launch_bounds__(256, 2)
gemm_mma(const float* __restrict__ A,  const float* __restrict__ W,
         const float* __restrict__ A2, const float* __restrict__ W2,
         const float* __restrict__ bias,
         const float* __restrict__ add1,
         float* __restrict__ C, int Nrows, int K, int Mtot, int do_relu)
{
    extern __shared__ __align__(16) char dsm[];
    const uint32_t sbase = smem_u32(dsm);

    const int tid    = threadIdx.x;
    const int wid    = tid >> 5;
    const int lane   = tid & 31;
    const int warp_m = wid >> 2;
    const int warp_n = wid & 3;
    const int g      = lane >> 2;
    const int t4     = (lane & 3) * 4;
    const int brow   = blockIdx.x * 128;
    const int bcol   = blockIdx.y * 64;

    float acc[4][2][4];
#pragma unroll
    for (int i = 0; i < 4; i++)
#pragma unroll
        for (int j = 0; j < 2; j++)
#pragma unroll
            for (int r = 0; r < 4; r++) acc[i][j][r] = 0.f;

    const int kch = K >> 5;
    const int nch = A2 ? kch * 2 : kch;

    // prologue: stage chunk 0 into buffer 0
    issue_tiles(A, W, K, Mtot, Nrows, brow, bcol, 0, tid,
                sbase + STG_A0, sbase + STG_B0);
    asm volatile("cp.async.commit_group;");

    for (int c = 0; c < nch; ++c) {
        // issue chunk c+1 into the other buffer, then wait for chunk c
        if (c + 1 < nch) {
            int cn   = c + 1;
            int pass = cn / kch;
            int k0   = (cn % kch) * 32;
            uint32_t sa = sbase + ((cn & 1) ? STG_A1 : STG_A0);
            uint32_t sb = sbase + ((cn & 1) ? STG_B1 : STG_B0);
            issue_tiles(pass ? A2 : A, pass ? W2 : W, K, Mtot, Nrows,
                        brow, bcol, k0, tid, sa, sb);
            asm volatile("cp.async.commit_group;");
            asm volatile("cp.async.wait_group 1;");
        } else {
            asm volatile("cp.async.wait_group 0;");
        }
        __syncthreads();   // staging visible to all + previous MMA done

        // ---- convert fp32 staging -> bf16 hi/lo tiles
        const char* stgA = dsm + ((c & 1) ? STG_A1 : STG_A0);
        const char* stgB = dsm + ((c & 1) ? STG_B1 : STG_B0);
#pragma unroll
        for (int t = 0; t < 4; ++t) {
            int idx = tid + t * 256;
            int r   = idx >> 3;
            int kg  = idx & 7;
            float4 v = *(const float4*)(stgA + r * ASTR + kg * 16);
            int off = r * SSTR + kg * 8;
            *(uint2*)(dsm + A_HI + off) =
                make_uint2(pack_hi(v.x, v.y), pack_hi(v.z, v.w));
            *(uint2*)(dsm + A_LO + off) =
                make_uint2(pack_lo(v.x, v.y), pack_lo(v.z, v.w));
        }
#pragma unroll
        for (int t = 0; t < 2; ++t) {
            int idx = tid + t * 256;
            int n   = idx & 63;
            int kg  = idx >> 6;
            float w0 = *(const float*)(stgB + (kg * 4 + 0) * 256 + n * 4);
            float w1 = *(const float*)(stgB + (kg * 4 + 1) * 256 + n * 4);
            float w2 = *(const float*)(stgB + (kg * 4 + 2) * 256 + n * 4);
            float w3 = *(const float*)(stgB + (kg * 4 + 3) * 256 + n * 4);
            int off = n * SSTR + kg * 8;
            *(uint2*)(dsm + B_HI + off) =
                make_uint2(pack_hi(w0, w1), pack_hi(w2, w3));
            *(uint2*)(dsm + B_LO + off) =
                make_uint2(pack_lo(w0, w1), pack_lo(w2, w3));
        }
        __syncthreads();   // bf16 tiles ready

        // ---- compute: 2 k-steps of 16
#pragma unroll
        for (int ks = 0; ks < 2; ++ks) {
            const int ko = ks * 32;
            unsigned aH[4][4], aL[4][4], bH[2][2], bL[2][2];
#pragma unroll
            for (int nt = 0; nt < 2; ++nt) {
                int nb = (warp_n * 16 + nt * 8 + g) * SSTR + t4 + ko;
                bH[nt][0] = *(const unsigned*)(dsm + B_HI + nb);
                bH[nt][1] = *(const unsigned*)(dsm + B_HI + nb + 16);
                bL[nt][0] = *(const unsigned*)(dsm + B_LO + nb);
                bL[nt][1] = *(const unsigned*)(dsm + B_LO + nb + 16);
            }
#pragma unroll
            for (int mt = 0; mt < 4; ++mt) {
                int mb = (warp_m * 64 + mt * 16 + g) * SSTR + t4 + ko;
                aH[mt][0] = *(const unsigned*)(dsm + A_HI + mb);
                aH[mt][1] = *(const unsigned*)(dsm + A_HI + mb + 8 * SSTR);
                aH[mt][2] = *(const unsigned*)(dsm + A_HI + mb + 16);
                aH[mt][3] = *(const unsigned*)(dsm + A_HI + mb + 8 * SSTR + 16);
                aL[mt][0] = *(const unsigned*)(dsm + A_LO + mb);
                aL[mt][1] = *(const unsigned*)(dsm + A_LO + mb + 8 * SSTR);
                aL[mt][2] = *(const unsigned*)(dsm + A_LO + mb + 16);
                aL[mt][3] = *(const unsigned*)(dsm + A_LO + mb + 8 * SSTR + 16);
            }
#pragma unroll
            for (int mt = 0; mt < 4; ++mt)
#pragma unroll
                for (int nt = 0; nt < 2; ++nt) {
                    mma_bf16(acc[mt][nt], aH[mt], bH[nt]);
                    mma_bf16(acc[mt][nt], aH[mt], bL[nt]);
                    mma_bf16(acc[mt][nt], aL[mt], bH[nt]);
                }
        }
    }

    // ---- epilogue
#pragma unroll
    for (int mt = 0; mt < 4; ++mt) {
#pragma unroll
        for (int nt = 0; nt < 2; ++nt) {
            int col = bcol + warp_n * 16 + nt * 8 + (lane & 3) * 2;
#pragma unroll
            for (int half = 0; half < 2; ++half) {
                int row = brow + warp_m * 64 + mt * 16 + g + half * 8;
                if (row >= Nrows) continue;
                float v0 = acc[mt][nt][half * 2 + 0];
                float v1 = acc[mt][nt][half * 2 + 1];
                if (bias) {
                    float2 b = *(const float2*)(bias + col);
                    v0 += b.x; v1 += b.y;
                }
                size_t o = (size_t)row * Mtot + col;
                if (add1) {
                    float2 a = *(const float2*)(add1 + o);
                    v0 += a.x; v1 += a.y;
                }
                if (do_relu) { v0 = fmaxf(v0, 0.f); v1 = fmaxf(v1, 0.f); }
                *(float2*)(C + o) = make_float2(v0, v1);
            }
        }
    }
}

// ---------------------------------------------------------------------------
// Weight + bias packing (one kernel)
// ---------------------------------------------------------------------------
__global__ void pack_wb(const float* __restrict__ w0,
                        const float* __restrict__ w1,
                        const float* __restrict__ w2,
                        const float* __restrict__ w3,
                        const float* __restrict__ w4,
                        const float* __restrict__ b1, const float* __restrict__ b2,
                        const float* __restrict__ b3, const float* __restrict__ b4,
                        float* __restrict__ Wp, float* __restrict__ bp)
{
    int idx = blockIdx.x * blockDim.x + threadIdx.x;
    const int NW4 = HID * MPK / 4;
    if (idx < NW4) {
        int row = idx / (MPK / 4);
        int col = (idx % (MPK / 4)) * 4;
        int b   = col >> 9;
        int c   = col & 511;
        const float* srcs[5] = {w0, w1, w2, w3, w4};
        *(float4*)(Wp + (size_t)row * MPK + col) =
            *(const float4*)(srcs[b] + (size_t)row * HC + c);
    } else if (idx < NW4 + MPK) {
        int col = idx - NW4;
        int b = col >> 9, c = col & 511;
        float v = 0.f;
        if (b == 1) v = b1[c];
        else if (b == 2) v = b2[c];
        else if (b == 3) v = b3[c];
        else if (b == 4) v = b4[c];
        bp[col] = v;
    }
}

// ---------------------------------------------------------------------------
// CSR build (by dst)
// ---------------------------------------------------------------------------
__global__ void deg_count(const int* __restrict__ dst, int* __restrict__ deg)
{
    int e = blockIdx.x * blockDim.x + threadIdx.x;
    if (e < EE) atomicAdd(&deg[dst[e]], 1);
}

__global__ void scan_offsets(const int* __restrict__ deg,
                             int* __restrict__ off, int* __restrict__ cur)
{
    extern __shared__ int sdeg[];
    __shared__ int wsum[32];
    const int t    = threadIdx.x;
    const int lane = t & 31;
    const int wid  = t >> 5;
    const int CH   = (NN + 1023) / 1024;

    for (int i = t; i < NN; i += 1024) sdeg[i] = deg[i];
    __syncthreads();

    int base = t * CH;
    int s = 0;
#pragma unroll
    for (int i = 0; i < CH; i++) {
        int idx = base + i;
        if (idx < NN) s += sdeg[idx];
    }
    int v = s;
#pragma unroll
    for (int o = 1; o < 32; o <<= 1) {
        int u = __shfl_up_sync(0xffffffffu, v, o);
        if (lane >= o) v += u;
    }
    if (lane == 31) wsum[wid] = v;
    __syncthreads();
    if (wid == 0) {
        int w = wsum[lane];
#pragma unroll
        for (int o = 1; o < 32; o <<= 1) {
            int u = __shfl_up_sync(0xffffffffu, w, o);
            if (lane >= o) w += u;
        }
        wsum[lane] = w;
    }
    __syncthreads();
    int excl = v - s + (wid ? wsum[wid - 1] : 0);
#pragma unroll
    for (int i = 0; i < CH; i++) {
        int idx = base + i;
        if (idx < NN) {
            off[idx] = excl;
            cur[idx] = excl;
            excl += sdeg[idx];
        }
    }
    if (t == 1023) off[NN] = excl;
}

__global__ void build_srcs(const int* __restrict__ src, const int* __restrict__ dst,
                           int* __restrict__ cur, int* __restrict__ srcs)
{
    int e = blockIdx.x * blockDim.x + threadIdx.x;
    if (e >= EE) return;
    int pos = atomicAdd(&cur[dst[e]], 1);
    srcs[pos] = src[e];
}

// ---------------------------------------------------------------------------
// GraphConv aggregation via CSR
// ---------------------------------------------------------------------------
__global__ void gconv_agg(const float* __restrict__ in,
                          const int* __restrict__ off,
                          const int* __restrict__ srcs,
                          float* __restrict__ agg)
{
    int d = blockIdx.x;
    int c = threadIdx.x;
    int e0 = off[d], e1 = off[d + 1];
    float s = 0.f;
    int i = e0;
    for (; i + 3 < e1; i += 4) {
        int s0 = srcs[i], s1 = srcs[i + 1], s2 = srcs[i + 2], s3 = srcs[i + 3];
        s += in[(size_t)s0 * HID + c] + in[(size_t)s1 * HID + c]
           + in[(size_t)s2 * HID + c] + in[(size_t)s3 * HID + c];
    }
    for (; i < e1; ++i)
        s += in[(size_t)srcs[i] * HID + c];
    agg[(size_t)d * HID + c] = s;
}

// ---------------------------------------------------------------------------
// Attention + transformer epilogue fused, 8 warps/node (2 warps per head)
// ---------------------------------------------------------------------------
__global__ void __launch_bounds__(256)
attn_fused(const float* __restrict__ pack,
           const int* __restrict__ off,
           const int* __restrict__ srcs,
           float* __restrict__ h2)
{
    __shared__ float s_m[4], s_den[4], s_acc[4][128];

    int d    = blockIdx.x;
    int w    = threadIdx.x >> 5;
    int lane = threadIdx.x & 31;
    int h    = w & 3;
    int half = w >> 2;
    int e0 = off[d], e1 = off[d + 1];
    int emid = (e0 + e1) >> 1;
    int lo = half ? emid : e0;
    int hi = half ? e1   : emid;

    const float* qp = pack + 512;
    const float* kp = pack + 1024;
    const float* vp = pack + 1536;

    float4 qv = *((const float4*)(qp + (size_t)d * MPK + h * HID) + lane);
    float4 acc = make_float4(0.f, 0.f, 0.f, 0.f);
    float mrun = NEGBIG, den = 0.f;

    int i = lo;
    for (; i + 1 < hi; i += 2) {
        int s0 = srcs[i], s1 = srcs[i + 1];
        float4 k0 = *((const float4*)(kp + (size_t)s0 * MPK + h * HID) + lane);
        float4 k1 = *((const float4*)(kp + (size_t)s1 * MPK + h * HID) + lane);
        float4 v0 = *((const float4*)(vp + (size_t)s0 * MPK + h * HID) + lane);
        float4 v1 = *((const float4*)(vp + (size_t)s1 * MPK + h * HID) + lane);
        float d0 = qv.x * k0.x + qv.y * k0.y + qv.z * k0.z + qv.w * k0.w;
        float d1 = qv.x * k1.x + qv.y * k1.y + qv.z * k1.z + qv.w * k1.w;
#pragma unroll
        for (int o = 16; o; o >>= 1) {
            d0 += __shfl_xor_sync(0xffffffffu, d0, o);
            d1 += __shfl_xor_sync(0xffffffffu, d1, o);
        }
        d0 *= 0.08838834764831843f;
        d1 *= 0.08838834764831843f;

        float mnew = fmaxf(mrun, d0);
        float corr = __expf(mrun - mnew);
        float wt   = __expf(d0 - mnew);
        den = den * corr + wt;
        acc.x = acc.x * corr + wt * v0.x;
        acc.y = acc.y * corr + wt * v0.y;
        acc.z = acc.z * corr + wt * v0.z;
        acc.w = acc.w * corr + wt * v0.w;
        mrun = mnew;

        mnew = fmaxf(mrun, d1);
        corr = __expf(mrun - mnew);
        wt   = __expf(d1 - mnew);
        den = den * corr + wt;
        acc.x = acc.x * corr + wt * v1.x;
        acc.y = acc.y * corr + wt * v1.y;
        acc.z = acc.z * corr + wt * v1.z;
        acc.w = acc.w * corr + wt * v1.w;
        mrun = mnew;
    }
    if (i < hi) {
        int s0 = srcs[i];
        float4 k0 = *((const float4*)(kp + (size_t)s0 * MPK + h * HID) + lane);
        float4 v0 = *((const float4*)(vp + (size_t)s0 * MPK + h * HID) + lane);
        float d0 = qv.x * k0.x + qv.y * k0.y + qv.z * k0.z + qv.w * k0.w;
#pragma unroll
        for (int o = 16; o; o >>= 1) d0 += __shfl_xor_sync(0xffffffffu, d0, o);
        d0 *= 0.08838834764831843f;
        float mnew = fmaxf(mrun, d0);
        float corr = __expf(mrun - mnew);
        float wt   = __expf(d0 - mnew);
        den = den * corr + wt;
        acc.x = acc.x * corr + wt * v0.x;
        acc.y = acc.y * corr + wt * v0.y;
        acc.z = acc.z * corr + wt * v0.z;
        acc.w = acc.w * corr + wt * v0.w;
        mrun = mnew;
    }

    if (half == 1) {
        if (lane == 0) { s_m[h] = mrun; s_den[h] = den; }
        *((float4*)&s_acc[h][0] + lane) = acc;
    }
    __syncthreads();
    if (half == 0) {
        float m1 = s_m[h], den1 = s_den[h];
        float4 a1 = *((const float4*)&s_acc[h][0] + lane);
        float mnew = fmaxf(mrun, m1);
        float c0 = __expf(mrun - mnew);
        float c1 = __expf(m1 - mnew);
        den = den * c0 + den1 * c1;
        acc.x = acc.x * c0 + a1.x * c1;
        acc.y = acc.y * c0 + a1.y * c1;
        acc.z = acc.z * c0 + a1.z * c1;
        acc.w = acc.w * c0 + a1.w * c1;

        float inv = 1.f / (den + 1e-16f);
        float4 ts = *((const float4*)(pack + 2048 + (size_t)d * MPK + h * HID) + lane);
        float4 sk = *((const float4*)(pack + 0    + (size_t)d * MPK + h * HID) + lane);
        float4 r;
        r.x = fmaxf(acc.x * inv + ts.x + sk.x, 0.f);
        r.y = fmaxf(acc.y * inv + ts.y + sk.y, 0.f);
        r.z = fmaxf(acc.z * inv + ts.z + sk.z, 0.f);
        r.w = fmaxf(acc.w * inv + ts.w + sk.w, 0.f);
        *((float4*)(h2 + (size_t)d * HC + h * HID) + lane) = r;
    }
}

// ---------------------------------------------------------------------------
// Pooling (batch sorted: accumulate runs, flush atomics on group change)
// ---------------------------------------------------------------------------
#define PB 64
__global__ void pool_accum(const float* __restrict__ h,
                           const int* __restrict__ batch,
                           float* __restrict__ pool, float* __restrict__ cnt)
{
    int c  = threadIdx.x;
    int n0 = blockIdx.x * PB;
    int n1 = min(n0 + PB, NN);
    float s = 0.f;
    int cb = batch[n0], count = 0;
    for (int n = n0; n < n1; ++n) {
        int b = batch[n];
        if (b != cb) {
            atomicAdd(&pool[cb * HID + c], s);
            if (c == 0) atomicAdd(&cnt[cb], (float)count);
            s = 0.f; count = 0; cb = b;
        }
        s += h[(size_t)n * HID + c];
        count++;
    }
    atomicAdd(&pool[cb * HID + c], s);
    if (c == 0) atomicAdd(&cnt[cb], (float)count);
}

__global__ void pool_fc(const float* __restrict__ pool,
                        const float* __restrict__ cnt,
                        const float* __restrict__ fcW,
                        const float* __restrict__ fcb,
                        float* __restrict__ out)
{
    int g = blockIdx.x;
    int c = threadIdx.x;
    float inv = 1.f / fmaxf(cnt[g], 1.f);
    float s = 0.f;
    for (int k = 0; k < HID; k++)
        s += pool[g * HID + k] * fcW[k * NCC + c];
    out[g * NCC + c] = s * inv + fcb[c];
}

// ---------------------------------------------------------------------------
// Launch
// ---------------------------------------------------------------------------
extern "C" void kernel_launch(void* const* d_in, const int* in_sizes, int n_in,
                              void* d_out, int out_size)
{
    const float* x        = (const float*)d_in[0];
    const int*   ei       = (const int*)  d_in[1];
    const int*   src      = ei;
    const int*   dst      = ei + EE;
    const int*   batch    = (const int*)  d_in[2];
    const float* c1_Wr    = (const float*)d_in[3];
    const float* c1_br    = (const float*)d_in[4];
    const float* c1_Wroot = (const float*)d_in[5];
    const float* tq_W  = (const float*)d_in[6];  const float* tq_b  = (const float*)d_in[7];
    const float* tk_W  = (const float*)d_in[8];  const float* tk_b  = (const float*)d_in[9];
    const float* tv_W  = (const float*)d_in[10]; const float* tv_b  = (const float*)d_in[11];
    const float* ts_W  = (const float*)d_in[12]; const float* ts_b  = (const float*)d_in[13];
    const float* skip_W = (const float*)d_in[14];
    const float* l1W    = (const float*)d_in[15]; const float* l1b = (const float*)d_in[16];
    const float* g1_Wr = (const float*)d_in[17]; const float* g1_br = (const float*)d_in[18];
    const float* g1_Wroot = (const float*)d_in[19];
    const float* g2_Wr = (const float*)d_in[20]; const float* g2_br = (const float*)d_in[21];
    const float* g2_Wroot = (const float*)d_in[22];
    const float* fc_W = (const float*)d_in[23]; const float* fc_b = (const float*)d_in[24];
    float* out = (float*)d_out;

    float *agg, *h, *h3, *h4, *h5, *pack, *h2, *Wpk, *bpk, *pool, *cnt;
    int *deg, *cur, *off, *srcs;
    cudaGetSymbolAddress((void**)&agg,  g_agg);
    cudaGetSymbolAddress((void**)&h,    g_h);
    cudaGetSymbolAddress((void**)&h3,   g_h3);
    cudaGetSymbolAddress((void**)&h4,   g_h4);
    cudaGetSymbolAddress((void**)&h5,   g_h5);
    cudaGetSymbolAddress((void**)&pack, g_pack);
    cudaGetSymbolAddress((void**)&h2,   g_h2);
    cudaGetSymbolAddress((void**)&Wpk,  g_Wpk);
    cudaGetSymbolAddress((void**)&bpk,  g_bpk);
    cudaGetSymbolAddress((void**)&pool, g_pool);
    cudaGetSymbolAddress((void**)&cnt,  g_cnt);
    cudaGetSymbolAddress((void**)&deg,  g_deg);
    cudaGetSymbolAddress((void**)&cur,  g_cur);
    cudaGetSymbolAddress((void**)&off,  g_off);
    cudaGetSymbolAddress((void**)&srcs, g_srcs);

    const int SCAN_SMEM = NN * (int)sizeof(int);
    cudaFuncSetAttribute(scan_offsets, cudaFuncAttributeMaxDynamicSharedMemorySize,
                         SCAN_SMEM);
    cudaFuncSetAttribute(gemm_mma, cudaFuncAttributeMaxDynamicSharedMemorySize,
                         GEMM_SMEM);

    const dim3 gb(256);
    const dim3 grid128((NN + 127) / 128, 2);
    const dim3 gridPK ((NN + 127) / 128, MPK / 64);

    // --- weight+bias packing (independent)
    pack_wb<<<(HID * MPK / 4 + MPK + 255) / 256, 256>>>(
        skip_W, tq_W, tk_W, tv_W, ts_W, tq_b, tk_b, tv_b, ts_b, Wpk, bpk);

    // --- CSR build (by dst)
    cudaMemsetAsync(deg, 0, NN * sizeof(int));
    deg_count<<<(EE + 255) / 256, 256>>>(dst, deg);
    scan_offsets<<<1, 1024, SCAN_SMEM>>>(deg, off, cur);
    build_srcs<<<(EE + 255) / 256, 256>>>(src, dst, cur, srcs);

    // --- conv1: h = relu( (agg x) @ Wr + br + x @ Wroot )
    gconv_agg<<<NN, 128>>>(x, off, srcs, agg);
    gemm_mma<<<grid128, gb, GEMM_SMEM>>>(agg, c1_Wr, x, c1_Wroot, c1_br,
                                         nullptr, h, NN, 128, 128, 1);

    // --- packed projections: [skip | q | k | v | ts] = h @ Wpk + bpk
    gemm_mma<<<gridPK, gb, GEMM_SMEM>>>(h, Wpk, nullptr, nullptr, bpk,
                                        nullptr, pack, NN, 128, MPK, 0);

    // --- attention + fused epilogue
    attn_fused<<<NN, 256>>>(pack, off, srcs, h2);

    // --- h3 = relu(h2 @ lin1_W + lin1_b)
    gemm_mma<<<grid128, gb, GEMM_SMEM>>>(h2, l1W, nullptr, nullptr, l1b,
                                         nullptr, h3, NN, 512, 128, 1);

    // --- gconv l1 with residual
    gconv_agg<<<NN, 128>>>(h3, off, srcs, agg);
    gemm_mma<<<grid128, gb, GEMM_SMEM>>>(agg, g1_Wr, h3, g1_Wroot, g1_br,
                                         h3, h4, NN, 128, 128, 1);

    // --- gconv l2 with residual
    gconv_agg<<<NN, 128>>>(h4, off, srcs, agg);
    gemm_mma<<<grid128, gb, GEMM_SMEM>>>(agg, g2_Wr, h4, g2_Wroot, g2_br,
                                         h4, h5, NN, 128, 128, 1);

    // --- mean pool + fc
    cudaMemsetAsync(pool, 0, (size_t)GG * HID * sizeof(float));
    cudaMemsetAsync(cnt,  0, (size_t)GG * sizeof(float));
    pool_accum<<<(NN + PB - 1) / PB, 128>>>(h5, batch, pool, cnt);
    pool_fc<<<GG, NCC>>>(pool, cnt, fc_W, fc_b, out);
}

// round 10
// speedup vs baseline: 1.2673x; 1.2673x over previous
#include <cuda_runtime.h>
#include <cuda_bf16.h>
#include <cuda_fp16.h>
#include <cstdint>

// Problem constants (fixed by the dataset)
#define NN   20000
#define EE   160000
#define HID  128
#define NHEADS 4
#define GG   64
#define NCC  8
#define HC   512
#define MPK  2560      // packed projection width: [skip | q | k | v | ts]
#define NEGBIG (-1.0e30f)

// ---------------------------------------------------------------------------
// Scratch (device globals: allocation-free contract)
// ---------------------------------------------------------------------------
__device__ float g_agg [NN * HID];
__device__ float g_h   [NN * HID];
__device__ float g_h3  [NN * HID];
__device__ float g_h4  [NN * HID];
__device__ float g_h5  [NN * HID];
__device__ float g_pack[(size_t)NN * MPK];
__device__ float g_h2  [NN * HC];
__device__ float g_Wpk [HID * MPK];
__device__ float g_bpk [MPK];
__device__ float g_pool[GG * HID];
__device__ float g_cnt [GG];
// CSR (by dst)
__device__ int   g_deg [NN];
__device__ int   g_cur [NN];
__device__ int   g_off [NN + 1];
__device__ int   g_srcs[EE];

// ---------------------------------------------------------------------------
// mma.sync fp16 GEMM (single MMA, f32 accumulate) + register-prefetch pipeline
// C[Nrows, Mtot] = op( A@W [+ A2@W2] [+bias] [+add1] ), W: [K, Mtot]
// CTA tile 128x64, BK=32. 8 warps (2m x 4n), warp tile 64x16, 2 CTAs/SM.
// Smem rows stride 80B -> fragment quad-load bank = (20g+t) mod 32, conflict-free.
// ---------------------------------------------------------------------------
#define A_T  0
#define B_T  10240
#define SSTR 80

__device__ __forceinline__ unsigned pack_h16(float x, float y) {
    __half2 p = __float22half2_rn(make_float2(x, y));
    return *(unsigned*)&p;
}

__device__ __forceinline__ void mma_f16(float* c, const unsigned* a, const unsigned* b) {
    asm volatile(
        "mma.sync.aligned.m16n8k16.row.col.f32.f16.f16.f32 "
        "{%0,%1,%2,%3}, {%4,%5,%6,%7}, {%8,%9}, {%0,%1,%2,%3};"
        : "+f"(c[0]), "+f"(c[1]), "+f"(c[2]), "+f"(c[3])
        : "r"(a[0]), "r"(a[1]), "r"(a[2]), "r"(a[3]), "r"(b[0]), "r"(b[1]));
}

__device__ __forceinline__ void load_tiles(const float* __restrict__ Ap,
                                           const float* __restrict__ Wp,
                                           int K, int Mtot, int Nrows,
                                           int brow, int bcol, int k0, int tid,
                                           float4 pa[4], float4 pb[2])
{
#pragma unroll
    for (int t = 0; t < 4; ++t) {
        int idx = tid + t * 256;
        int r   = idx >> 3;
        int kg  = idx & 7;
        pa[t] = make_float4(0.f, 0.f, 0.f, 0.f);
        if (brow + r < Nrows)
            pa[t] = *(const float4*)(Ap + (size_t)(brow + r) * K + k0 + kg * 4);
    }
#pragma unroll
    for (int t = 0; t < 2; ++t) {
        int idx = tid + t * 256;
        int n   = idx & 63;
        int kg  = idx >> 6;
        const float* wp = Wp + (size_t)(k0 + kg * 4) * Mtot + bcol + n;
        pb[t] = make_float4(wp[0], wp[Mtot], wp[2 * (size_t)Mtot],
                            wp[3 * (size_t)Mtot]);
    }
}

__global__ void __launch_bounds__(256, 2)
gemm_mma(const float* __restrict__ A,  const float* __restrict__ W,
         const float* __restrict__ A2, const float* __restrict__ W2,
         const float* __restrict__ bias,
         const float* __restrict__ add1,
         float* __restrict__ C, int Nrows, int K, int Mtot, int do_relu)
{
    __shared__ __align__(16) char smem[15360];

    const int tid    = threadIdx.x;
    const int wid    = tid >> 5;
    const int lane   = tid & 31;
    const int warp_m = wid >> 2;
    const int warp_n = wid & 3;
    const int g      = lane >> 2;
    const int t4     = (lane & 3) * 4;
    const int brow   = blockIdx.x * 128;
    const int bcol   = blockIdx.y * 64;

    float acc[4][2][4];
#pragma unroll
    for (int i = 0; i < 4; i++)
#pragma unroll
        for (int j = 0; j < 2; j++)
#pragma unroll
            for (int r = 0; r < 4; r++) acc[i][j][r] = 0.f;

    const int kch = K >> 5;
    const int nch = A2 ? kch * 2 : kch;

    float4 pa[4], pb[2];
    load_tiles(A, W, K, Mtot, Nrows, brow, bcol, 0, tid, pa, pb);

    for (int c = 0; c < nch; ++c) {
        __syncthreads();   // previous compute done; smem free

        // ---- store prefetched regs -> smem (convert fp32 -> fp16)
#pragma unroll
        for (int t = 0; t < 4; ++t) {
            int idx = tid + t * 256;
            int r   = idx >> 3;
            int kg  = idx & 7;
            *(uint2*)(smem + A_T + r * SSTR + kg * 8) =
                make_uint2(pack_h16(pa[t].x, pa[t].y), pack_h16(pa[t].z, pa[t].w));
        }
#pragma unroll
        for (int t = 0; t < 2; ++t) {
            int idx = tid + t * 256;
            int n   = idx & 63;
            int kg  = idx >> 6;
            *(uint2*)(smem + B_T + n * SSTR + kg * 8) =
                make_uint2(pack_h16(pb[t].x, pb[t].y), pack_h16(pb[t].z, pb[t].w));
        }

        // ---- issue next chunk's global loads (overlap with MMA below)
        if (c + 1 < nch) {
            int cn   = c + 1;
            int pass = cn / kch;
            int k0   = (cn % kch) * 32;
            load_tiles(pass ? A2 : A, pass ? W2 : W, K, Mtot, Nrows,
                       brow, bcol, k0, tid, pa, pb);
        }
        __syncthreads();   // smem tiles ready

        // ---- compute: 2 k-steps of 16
#pragma unroll
        for (int ks = 0; ks < 2; ++ks) {
            const int ko = ks * 32;          // bytes (16 fp16)
            unsigned aF[4][4], bF[2][2];
#pragma unroll
            for (int nt = 0; nt < 2; ++nt) {
                int nb = (warp_n * 16 + nt * 8 + g) * SSTR + t4 + ko;
                bF[nt][0] = *(const unsigned*)(smem + B_T + nb);
                bF[nt][1] = *(const unsigned*)(smem + B_T + nb + 16);
            }
#pragma unroll
            for (int mt = 0; mt < 4; ++mt) {
                int mb = (warp_m * 64 + mt * 16 + g) * SSTR + t4 + ko;
                aF[mt][0] = *(const unsigned*)(smem + A_T + mb);
                aF[mt][1] = *(const unsigned*)(smem + A_T + mb + 8 * SSTR);
                aF[mt][2] = *(const unsigned*)(smem + A_T + mb + 16);
                aF[mt][3] = *(const unsigned*)(smem + A_T + mb + 8 * SSTR + 16);
            }
#pragma unroll
            for (int mt = 0; mt < 4; ++mt)
#pragma unroll
                for (int nt = 0; nt < 2; ++nt)
                    mma_f16(acc[mt][nt], aF[mt], bF[nt]);
        }
    }

    // ---- epilogue
#pragma unroll
    for (int mt = 0; mt < 4; ++mt) {
#pragma unroll
        for (int nt = 0; nt < 2; ++nt) {
            int col = bcol + warp_n * 16 + nt * 8 + (lane & 3) * 2;
#pragma unroll
            for (int half = 0; half < 2; ++half) {
                int row = brow + warp_m * 64 + mt * 16 + g + half * 8;
                if (row >= Nrows) continue;
                float v0 = acc[mt][nt][half * 2 + 0];
                float v1 = acc[mt][nt][half * 2 + 1];
                if (bias) {
                    float2 b = *(const float2*)(bias + col);
                    v0 += b.x; v1 += b.y;
                }
                size_t o = (size_t)row * Mtot + col;
                if (add1) {
                    float2 a = *(const float2*)(add1 + o);
                    v0 += a.x; v1 += a.y;
                }
                if (do_relu) { v0 = fmaxf(v0, 0.f); v1 = fmaxf(v1, 0.f); }
                *(float2*)(C + o) = make_float2(v0, v1);
            }
        }
    }
}

// ---------------------------------------------------------------------------
// Weight + bias packing (one kernel)
// ---------------------------------------------------------------------------
__global__ void pack_wb(const float* __restrict__ w0,
                        const float* __restrict__ w1,
                        const float* __restrict__ w2,
                        const float* __restrict__ w3,
                        const float* __restrict__ w4,
                        const float* __restrict__ b1, const float* __restrict__ b2,
                        const float* __restrict__ b3, const float* __restrict__ b4,
                        float* __restrict__ Wp, float* __restrict__ bp)
{
    int idx = blockIdx.x * blockDim.x + threadIdx.x;
    const int NW4 = HID * MPK / 4;
    if (idx < NW4) {
        int row = idx / (MPK / 4);
        int col = (idx % (MPK / 4)) * 4;
        int b   = col >> 9;
        int c   = col & 511;
        const float* srcs[5] = {w0, w1, w2, w3, w4};
        *(float4*)(Wp + (size_t)row * MPK + col) =
            *(const float4*)(srcs[b] + (size_t)row * HC + c);
    } else if (idx < NW4 + MPK) {
        int col = idx - NW4;
        int b = col >> 9, c = col & 511;
        float v = 0.f;
        if (b == 1) v = b1[c];
        else if (b == 2) v = b2[c];
        else if (b == 3) v = b3[c];
        else if (b == 4) v = b4[c];
        bp[col] = v;
    }
}

// ---------------------------------------------------------------------------
// CSR build (by dst)
// ---------------------------------------------------------------------------
__global__ void deg_count(const int* __restrict__ dst, int* __restrict__ deg)
{
    int e = blockIdx.x * blockDim.x + threadIdx.x;
    if (e < EE) atomicAdd(&deg[dst[e]], 1);
}

__global__ void scan_offsets(const int* __restrict__ deg,
                             int* __restrict__ off, int* __restrict__ cur)
{
    extern __shared__ int sdeg[];
    __shared__ int wsum[32];
    const int t    = threadIdx.x;
    const int lane = t & 31;
    const int wid  = t >> 5;
    const int CH   = (NN + 1023) / 1024;

    for (int i = t; i < NN; i += 1024) sdeg[i] = deg[i];
    __syncthreads();

    int base = t * CH;
    int s = 0;
#pragma unroll
    for (int i = 0; i < CH; i++) {
        int idx = base + i;
        if (idx < NN) s += sdeg[idx];
    }
    int v = s;
#pragma unroll
    for (int o = 1; o < 32; o <<= 1) {
        int u = __shfl_up_sync(0xffffffffu, v, o);
        if (lane >= o) v += u;
    }
    if (lane == 31) wsum[wid] = v;
    __syncthreads();
    if (wid == 0) {
        int w = wsum[lane];
#pragma unroll
        for (int o = 1; o < 32; o <<= 1) {
            int u = __shfl_up_sync(0xffffffffu, w, o);
            if (lane >= o) w += u;
        }
        wsum[lane] = w;
    }
    __syncthreads();
    int excl = v - s + (wid ? wsum[wid - 1] : 0);
#pragma unroll
    for (int i = 0; i < CH; i++) {
        int idx = base + i;
        if (idx < NN) {
            off[idx] = excl;
            cur[idx] = excl;
            excl += sdeg[idx];
        }
    }
    if (t == 1023) off[NN] = excl;
}

__global__ void build_srcs(const int* __restrict__ src, const int* __restrict__ dst,
                           int* __restrict__ cur, int* __restrict__ srcs)
{
    int e = blockIdx.x * blockDim.x + threadIdx.x;
    if (e >= EE) return;
    int pos = atomicAdd(&cur[dst[e]], 1);
    srcs[pos] = src[e];
}

// ---------------------------------------------------------------------------
// GraphConv aggregation via CSR
// ---------------------------------------------------------------------------
__global__ void gconv_agg(const float* __restrict__ in,
                          const int* __restrict__ off,
                          const int* __restrict__ srcs,
                          float* __restrict__ agg)
{
    int d = blockIdx.x;
    int c = threadIdx.x;
    int e0 = off[d], e1 = off[d + 1];
    float s = 0.f;
    int i = e0;
    for (; i + 3 < e1; i += 4) {
        int s0 = srcs[i], s1 = srcs[i + 1], s2 = srcs[i + 2], s3 = srcs[i + 3];
        s += in[(size_t)s0 * HID + c] + in[(size_t)s1 * HID + c]
           + in[(size_t)s2 * HID + c] + in[(size_t)s3 * HID + c];
    }
    for (; i < e1; ++i)
        s += in[(size_t)srcs[i] * HID + c];
    agg[(size_t)d * HID + c] = s;
}

// ---------------------------------------------------------------------------
// Attention + transformer epilogue fused, 8 warps/node (2 warps per head)
// ---------------------------------------------------------------------------
__global__ void __launch_bounds__(256)
attn_fused(const float* __restrict__ pack,
           const int* __restrict__ off,
           const int* __restrict__ srcs,
           float* __restrict__ h2)
{
    __shared__ float s_m[4], s_den[4], s_acc[4][128];

    int d    = blockIdx.x;
    int w    = threadIdx.x >> 5;
    int lane = threadIdx.x & 31;
    int h    = w & 3;
    int half = w >> 2;
    int e0 = off[d], e1 = off[d + 1];
    int emid = (e0 + e1) >> 1;
    int lo = half ? emid : e0;
    int hi = half ? e1   : emid;

    const float* qp = pack + 512;
    const float* kp = pack + 1024;
    const float* vp = pack + 1536;

    float4 qv = *((const float4*)(qp + (size_t)d * MPK + h * HID) + lane);
    float4 acc = make_float4(0.f, 0.f, 0.f, 0.f);
    float mrun = NEGBIG, den = 0.f;

    int i = lo;
    for (; i + 1 < hi; i += 2) {
        int s0 = srcs[i], s1 = srcs[i + 1];
        float4 k0 = *((const float4*)(kp + (size_t)s0 * MPK + h * HID) + lane);
        float4 k1 = *((const float4*)(kp + (size_t)s1 * MPK + h * HID) + lane);
        float4 v0 = *((const float4*)(vp + (size_t)s0 * MPK + h * HID) + lane);
        float4 v1 = *((const float4*)(vp + (size_t)s1 * MPK + h * HID) + lane);
        float d0 = qv.x * k0.x + qv.y * k0.y + qv.z * k0.z + qv.w * k0.w;
        float d1 = qv.x * k1.x + qv.y * k1.y + qv.z * k1.z + qv.w * k1.w;
#pragma unroll
        for (int o = 16; o; o >>= 1) {
            d0 += __shfl_xor_sync(0xffffffffu, d0, o);
            d1 += __shfl_xor_sync(0xffffffffu, d1, o);
        }
        d0 *= 0.08838834764831843f;
        d1 *= 0.08838834764831843f;

        float mnew = fmaxf(mrun, d0);
        float corr = __expf(mrun - mnew);
        float wt   = __expf(d0 - mnew);
        den = den * corr + wt;
        acc.x = acc.x * corr + wt * v0.x;
        acc.y = acc.y * corr + wt * v0.y;
        acc.z = acc.z * corr + wt * v0.z;
        acc.w = acc.w * corr + wt * v0.w;
        mrun = mnew;

        mnew = fmaxf(mrun, d1);
        corr = __expf(mrun - mnew);
        wt   = __expf(d1 - mnew);
        den = den * corr + wt;
        acc.x = acc.x * corr + wt * v1.x;
        acc.y = acc.y * corr + wt * v1.y;
        acc.z = acc.z * corr + wt * v1.z;
        acc.w = acc.w * corr + wt * v1.w;
        mrun = mnew;
    }
    if (i < hi) {
        int s0 = srcs[i];
        float4 k0 = *((const float4*)(kp + (size_t)s0 * MPK + h * HID) + lane);
        float4 v0 = *((const float4*)(vp + (size_t)s0 * MPK + h * HID) + lane);
        float d0 = qv.x * k0.x + qv.y * k0.y + qv.z * k0.z + qv.w * k0.w;
#pragma unroll
        for (int o = 16; o; o >>= 1) d0 += __shfl_xor_sync(0xffffffffu, d0, o);
        d0 *= 0.08838834764831843f;
        float mnew = fmaxf(mrun, d0);
        float corr = __expf(mrun - mnew);
        float wt   = __expf(d0 - mnew);
        den = den * corr + wt;
        acc.x = acc.x * corr + wt * v0.x;
        acc.y = acc.y * corr + wt * v0.y;
        acc.z = acc.z * corr + wt * v0.z;
        acc.w = acc.w * corr + wt * v0.w;
        mrun = mnew;
    }

    if (half == 1) {
        if (lane == 0) { s_m[h] = mrun; s_den[h] = den; }
        *((float4*)&s_acc[h][0] + lane) = acc;
    }
    __syncthreads();
    if (half == 0) {
        float m1 = s_m[h], den1 = s_den[h];
        float4 a1 = *((const float4*)&s_acc[h][0] + lane);
        float mnew = fmaxf(mrun, m1);
        float c0 = __expf(mrun - mnew);
        float c1 = __expf(m1 - mnew);
        den = den * c0 + den1 * c1;
        acc.x = acc.x * c0 + a1.x * c1;
        acc.y = acc.y * c0 + a1.y * c1;
        acc.z = acc.z * c0 + a1.z * c1;
        acc.w = acc.w * c0 + a1.w * c1;

        float inv = 1.f / (den + 1e-16f);
        float4 ts = *((const float4*)(pack + 2048 + (size_t)d * MPK + h * HID) + lane);
        float4 sk = *((const float4*)(pack + 0    + (size_t)d * MPK + h * HID) + lane);
        float4 r;
        r.x = fmaxf(acc.x * inv + ts.x + sk.x, 0.f);
        r.y = fmaxf(acc.y * inv + ts.y + sk.y, 0.f);
        r.z = fmaxf(acc.z * inv + ts.z + sk.z, 0.f);
        r.w = fmaxf(acc.w * inv + ts.w + sk.w, 0.f);
        *((float4*)(h2 + (size_t)d * HC + h * HID) + lane) = r;
    }
}

// ---------------------------------------------------------------------------
// Pooling (batch sorted: accumulate runs, flush atomics on group change)
// ---------------------------------------------------------------------------
#define PB 64
__global__ void pool_accum(const float* __restrict__ h,
                           const int* __restrict__ batch,
                           float* __restrict__ pool, float* __restrict__ cnt)
{
    int c  = threadIdx.x;
    int n0 = blockIdx.x * PB;
    int n1 = min(n0 + PB, NN);
    float s = 0.f;
    int cb = batch[n0], count = 0;
    for (int n = n0; n < n1; ++n) {
        int b = batch[n];
        if (b != cb) {
            atomicAdd(&pool[cb * HID + c], s);
            if (c == 0) atomicAdd(&cnt[cb], (float)count);
            s = 0.f; count = 0; cb = b;
        }
        s += h[(size_t)n * HID + c];
        count++;
    }
    atomicAdd(&pool[cb * HID + c], s);
    if (c == 0) atomicAdd(&cnt[cb], (float)count);
}

__global__ void pool_fc(const float* __restrict__ pool,
                        const float* __restrict__ cnt,
                        const float* __restrict__ fcW,
                        const float* __restrict__ fcb,
                        float* __restrict__ out)
{
    int g = blockIdx.x;
    int c = threadIdx.x;
    float inv = 1.f / fmaxf(cnt[g], 1.f);
    float s = 0.f;
    for (int k = 0; k < HID; k++)
        s += pool[g * HID + k] * fcW[k * NCC + c];
    out[g * NCC + c] = s * inv + fcb[c];
}

// ---------------------------------------------------------------------------
// Launch
// ---------------------------------------------------------------------------
extern "C" void kernel_launch(void* const* d_in, const int* in_sizes, int n_in,
                              void* d_out, int out_size)
{
    const float* x        = (const float*)d_in[0];
    const int*   ei       = (const int*)  d_in[1];
    const int*   src      = ei;
    const int*   dst      = ei + EE;
    const int*   batch    = (const int*)  d_in[2];
    const float* c1_Wr    = (const float*)d_in[3];
    const float* c1_br    = (const float*)d_in[4];
    const float* c1_Wroot = (const float*)d_in[5];
    const float* tq_W  = (const float*)d_in[6];  const float* tq_b  = (const float*)d_in[7];
    const float* tk_W  = (const float*)d_in[8];  const float* tk_b  = (const float*)d_in[9];
    const float* tv_W  = (const float*)d_in[10]; const float* tv_b  = (const float*)d_in[11];
    const float* ts_W  = (const float*)d_in[12]; const float* ts_b  = (const float*)d_in[13];
    const float* skip_W = (const float*)d_in[14];
    const float* l1W    = (const float*)d_in[15]; const float* l1b = (const float*)d_in[16];
    const float* g1_Wr = (const float*)d_in[17]; const float* g1_br = (const float*)d_in[18];
    const float* g1_Wroot = (const float*)d_in[19];
    const float* g2_Wr = (const float*)d_in[20]; const float* g2_br = (const float*)d_in[21];
    const float* g2_Wroot = (const float*)d_in[22];
    const float* fc_W = (const float*)d_in[23]; const float* fc_b = (const float*)d_in[24];
    float* out = (float*)d_out;

    float *agg, *h, *h3, *h4, *h5, *pack, *h2, *Wpk, *bpk, *pool, *cnt;
    int *deg, *cur, *off, *srcs;
    cudaGetSymbolAddress((void**)&agg,  g_agg);
    cudaGetSymbolAddress((void**)&h,    g_h);
    cudaGetSymbolAddress((void**)&h3,   g_h3);
    cudaGetSymbolAddress((void**)&h4,   g_h4);
    cudaGetSymbolAddress((void**)&h5,   g_h5);
    cudaGetSymbolAddress((void**)&pack, g_pack);
    cudaGetSymbolAddress((void**)&h2,   g_h2);
    cudaGetSymbolAddress((void**)&Wpk,  g_Wpk);
    cudaGetSymbolAddress((void**)&bpk,  g_bpk);
    cudaGetSymbolAddress((void**)&pool, g_pool);
    cudaGetSymbolAddress((void**)&cnt,  g_cnt);
    cudaGetSymbolAddress((void**)&deg,  g_deg);
    cudaGetSymbolAddress((void**)&cur,  g_cur);
    cudaGetSymbolAddress((void**)&off,  g_off);
    cudaGetSymbolAddress((void**)&srcs, g_srcs);

    const int SCAN_SMEM = NN * (int)sizeof(int);
    cudaFuncSetAttribute(scan_offsets, cudaFuncAttributeMaxDynamicSharedMemorySize,
                         SCAN_SMEM);

    const dim3 gb(256);
    const dim3 grid128((NN + 127) / 128, 2);
    const dim3 gridPK ((NN + 127) / 128, MPK / 64);

    // --- weight+bias packing (independent)
    pack_wb<<<(HID * MPK / 4 + MPK + 255) / 256, 256>>>(
        skip_W, tq_W, tk_W, tv_W, ts_W, tq_b, tk_b, tv_b, ts_b, Wpk, bpk);

    // --- CSR build (by dst)
    cudaMemsetAsync(deg, 0, NN * sizeof(int));
    deg_count<<<(EE + 255) / 256, 256>>>(dst, deg);
    scan_offsets<<<1, 1024, SCAN_SMEM>>>(deg, off, cur);
    build_srcs<<<(EE + 255) / 256, 256>>>(src, dst, cur, srcs);

    // --- conv1: h = relu( (agg x) @ Wr + br + x @ Wroot )
    gconv_agg<<<NN, 128>>>(x, off, srcs, agg);
    gemm_mma<<<grid128, gb>>>(agg, c1_Wr, x, c1_Wroot, c1_br,
                              nullptr, h, NN, 128, 128, 1);

    // --- packed projections: [skip | q | k | v | ts] = h @ Wpk + bpk
    gemm_mma<<<gridPK, gb>>>(h, Wpk, nullptr, nullptr, bpk,
                             nullptr, pack, NN, 128, MPK, 0);

    // --- attention + fused epilogue
    attn_fused<<<NN, 256>>>(pack, off, srcs, h2);

    // --- h3 = relu(h2 @ lin1_W + lin1_b)
    gemm_mma<<<grid128, gb>>>(h2, l1W, nullptr, nullptr, l1b,
                              nullptr, h3, NN, 512, 128, 1);

    // --- gconv l1 with residual
    gconv_agg<<<NN, 128>>>(h3, off, srcs, agg);
    gemm_mma<<<grid128, gb>>>(agg, g1_Wr, h3, g1_Wroot, g1_br,
                              h3, h4, NN, 128, 128, 1);

    // --- gconv l2 with residual
    gconv_agg<<<NN, 128>>>(h4, off, srcs, agg);
    gemm_mma<<<grid128, gb>>>(agg, g2_Wr, h4, g2_Wroot, g2_br,
                              h4, h5, NN, 128, 128, 1);

    // --- mean pool + fc
    cudaMemsetAsync(pool, 0, (size_t)GG * HID * sizeof(float));
    cudaMemsetAsync(cnt,  0, (size_t)GG * sizeof(float));
    pool_accum<<<(NN + PB - 1) / PB, 128>>>(h5, batch, pool, cnt);
    pool_fc<<<GG, NCC>>>(pool, cnt, fc_W, fc_b, out);
}

// round 12
// speedup vs baseline: 1.3468x; 1.0627x over previous
#include <cuda_runtime.h>
#include <cuda_bf16.h>
#include <cuda_fp16.h>
#include <cstdint>

// Problem constants (fixed by the dataset)
#define NN   20000
#define EE   160000
#define HID  128
#define NHEADS 4
#define GG   64
#define NCC  8
#define HC   512
#define MPK  2560      // packed projection width: [skip | q | k | v | ts]
#define KVW  1536      // fp16 side-band width: [q(512) | (k128,v128) x 4 heads]
#define NEGBIG (-1.0e30f)

// ---------------------------------------------------------------------------
// Scratch (device globals: allocation-free contract)
// ---------------------------------------------------------------------------
__device__ float  g_agg [NN * HID];
__device__ float  g_h   [NN * HID];
__device__ float  g_h3  [NN * HID];
__device__ float  g_h4  [NN * HID];
__device__ float  g_h5  [NN * HID];
__device__ float  g_pack[(size_t)NN * MPK];   // fp32: skip + ts slots used
__device__ __half g_kvq [(size_t)NN * KVW];   // fp16: q,k,v compact
__device__ float  g_h2  [NN * HC];
__device__ float  g_Wpk [HID * MPK];
__device__ float  g_bpk [MPK];
__device__ float  g_pool[GG * HID];
__device__ float  g_cnt [GG];
// CSR (by dst)
__device__ int    g_deg [NN];
__device__ int    g_cur [NN];
__device__ int    g_off [NN + 1];
__device__ int    g_srcs[EE];

// ---------------------------------------------------------------------------
// mma.sync fp16 GEMM (single MMA, f32 accumulate) + register-prefetch pipeline
// C[Nrows, Mtot] = op( A@W [+ A2@W2] [+bias] [+add1] ), W: [K, Mtot]
// Optional: cols [512,2048) diverted to fp16 side-band C16 (q/k/v layout).
// CTA tile 128x64, BK=32. 8 warps (2m x 4n), warp tile 64x16, 2 CTAs/SM.
// ---------------------------------------------------------------------------
#define A_T  0
#define B_T  10240
#define SSTR 80

__device__ __forceinline__ unsigned pack_h16(float x, float y) {
    __half2 p = __float22half2_rn(make_float2(x, y));
    return *(unsigned*)&p;
}

__device__ __forceinline__ void mma_f16(float* c, const unsigned* a, const unsigned* b) {
    asm volatile(
        "mma.sync.aligned.m16n8k16.row.col.f32.f16.f16.f32 "
        "{%0,%1,%2,%3}, {%4,%5,%6,%7}, {%8,%9}, {%0,%1,%2,%3};"
        : "+f"(c[0]), "+f"(c[1]), "+f"(c[2]), "+f"(c[3])
        : "r"(a[0]), "r"(a[1]), "r"(a[2]), "r"(a[3]), "r"(b[0]), "r"(b[1]));
}

__device__ __forceinline__ void load_tiles(const float* __restrict__ Ap,
                                           const float* __restrict__ Wp,
                                           int K, int Mtot, int Nrows,
                                           int brow, int bcol, int k0, int tid,
                                           float4 pa[4], float4 pb[2])
{
#pragma unroll
    for (int t = 0; t < 4; ++t) {
        int idx = tid + t * 256;
        int r   = idx >> 3;
        int kg  = idx & 7;
        pa[t] = make_float4(0.f, 0.f, 0.f, 0.f);
        if (brow + r < Nrows)
            pa[t] = *(const float4*)(Ap + (size_t)(brow + r) * K + k0 + kg * 4);
    }
#pragma unroll
    for (int t = 0; t < 2; ++t) {
        int idx = tid + t * 256;
        int n   = idx & 63;
        int kg  = idx >> 6;
        const float* wp = Wp + (size_t)(k0 + kg * 4) * Mtot + bcol + n;
        pb[t] = make_float4(wp[0], wp[Mtot], wp[2 * (size_t)Mtot],
                            wp[3 * (size_t)Mtot]);
    }
}

__global__ void __launch_bounds__(256, 2)
gemm_mma(const float* __restrict__ A,  const float* __restrict__ W,
         const float* __restrict__ A2, const float* __restrict__ W2,
         const float* __restrict__ bias,
         const float* __restrict__ add1,
         float* __restrict__ C, __half* __restrict__ C16,
         int Nrows, int K, int Mtot, int do_relu)
{
    __shared__ __align__(16) char smem[15360];

    const int tid    = threadIdx.x;
    const int wid    = tid >> 5;
    const int lane   = tid & 31;
    const int warp_m = wid >> 2;
    const int warp_n = wid & 3;
    const int g      = lane >> 2;
    const int t4     = (lane & 3) * 4;
    const int brow   = blockIdx.x * 128;
    const int bcol   = blockIdx.y * 64;

    float acc[4][2][4];
#pragma unroll
    for (int i = 0; i < 4; i++)
#pragma unroll
        for (int j = 0; j < 2; j++)
#pragma unroll
            for (int r = 0; r < 4; r++) acc[i][j][r] = 0.f;

    const int kch = K >> 5;
    const int nch = A2 ? kch * 2 : kch;

    float4 pa[4], pb[2];
    load_tiles(A, W, K, Mtot, Nrows, brow, bcol, 0, tid, pa, pb);

    for (int c = 0; c < nch; ++c) {
        __syncthreads();   // previous compute done; smem free

        // ---- store prefetched regs -> smem (convert fp32 -> fp16)
#pragma unroll
        for (int t = 0; t < 4; ++t) {
            int idx = tid + t * 256;
            int r   = idx >> 3;
            int kg  = idx & 7;
            *(uint2*)(smem + A_T + r * SSTR + kg * 8) =
                make_uint2(pack_h16(pa[t].x, pa[t].y), pack_h16(pa[t].z, pa[t].w));
        }
#pragma unroll
        for (int t = 0; t < 2; ++t) {
            int idx = tid + t * 256;
            int n   = idx & 63;
            int kg  = idx >> 6;
            *(uint2*)(smem + B_T + n * SSTR + kg * 8) =
                make_uint2(pack_h16(pb[t].x, pb[t].y), pack_h16(pb[t].z, pb[t].w));
        }

        // ---- issue next chunk's global loads (overlap with MMA below)
        if (c + 1 < nch) {
            int cn   = c + 1;
            int pass = cn / kch;
            int k0   = (cn % kch) * 32;
            load_tiles(pass ? A2 : A, pass ? W2 : W, K, Mtot, Nrows,
                       brow, bcol, k0, tid, pa, pb);
        }
        __syncthreads();   // smem tiles ready

        // ---- compute: 2 k-steps of 16
#pragma unroll
        for (int ks = 0; ks < 2; ++ks) {
            const int ko = ks * 32;
            unsigned aF[4][4], bF[2][2];
#pragma unroll
            for (int nt = 0; nt < 2; ++nt) {
                int nb = (warp_n * 16 + nt * 8 + g) * SSTR + t4 + ko;
                bF[nt][0] = *(const unsigned*)(smem + B_T + nb);
                bF[nt][1] = *(const unsigned*)(smem + B_T + nb + 16);
            }
#pragma unroll
            for (int mt = 0; mt < 4; ++mt) {
                int mb = (warp_m * 64 + mt * 16 + g) * SSTR + t4 + ko;
                aF[mt][0] = *(const unsigned*)(smem + A_T + mb);
                aF[mt][1] = *(const unsigned*)(smem + A_T + mb + 8 * SSTR);
                aF[mt][2] = *(const unsigned*)(smem + A_T + mb + 16);
                aF[mt][3] = *(const unsigned*)(smem + A_T + mb + 8 * SSTR + 16);
            }
#pragma unroll
            for (int mt = 0; mt < 4; ++mt)
#pragma unroll
                for (int nt = 0; nt < 2; ++nt)
                    mma_f16(acc[mt][nt], aF[mt], bF[nt]);
        }
    }

    // ---- epilogue
#pragma unroll
    for (int mt = 0; mt < 4; ++mt) {
#pragma unroll
        for (int nt = 0; nt < 2; ++nt) {
            int col = bcol + warp_n * 16 + nt * 8 + (lane & 3) * 2;
#pragma unroll
            for (int half = 0; half < 2; ++half) {
                int row = brow + warp_m * 64 + mt * 16 + g + half * 8;
                if (row >= Nrows) continue;
                float v0 = acc[mt][nt][half * 2 + 0];
                float v1 = acc[mt][nt][half * 2 + 1];
                if (bias) {
                    float2 b = *(const float2*)(bias + col);
                    v0 += b.x; v1 += b.y;
                }
                // fp16 side-band for q/k/v columns
                if (C16) {
                    int cg = col - 512;
                    if (cg >= 0 && cg < 1536) {
                        int hoff;
                        if (cg < 512) {
                            hoff = cg;                                    // q
                        } else if (cg < 1024) {
                            int t2 = cg - 512;                            // k
                            hoff = 512 + ((t2 >> 7) << 8) + (t2 & 127);
                        } else {
                            int t2 = cg - 1024;                           // v
                            hoff = 640 + ((t2 >> 7) << 8) + (t2 & 127);
                        }
                        *(__half2*)(C16 + (size_t)row * KVW + hoff) =
                            __floats2half2_rn(v0, v1);
                        continue;
                    }
                }
                size_t o = (size_t)row * Mtot + col;
                if (add1) {
                    float2 a = *(const float2*)(add1 + o);
                    v0 += a.x; v1 += a.y;
                }
                if (do_relu) { v0 = fmaxf(v0, 0.f); v1 = fmaxf(v1, 0.f); }
                *(float2*)(C + o) = make_float2(v0, v1);
            }
        }
    }
}

// ---------------------------------------------------------------------------
// Weight + bias packing (one kernel)
// ---------------------------------------------------------------------------
__global__ void pack_wb(const float* __restrict__ w0,
                        const float* __restrict__ w1,
                        const float* __restrict__ w2,
                        const float* __restrict__ w3,
                        const float* __restrict__ w4,
                        const float* __restrict__ b1, const float* __restrict__ b2,
                        const float* __restrict__ b3, const float* __restrict__ b4,
                        float* __restrict__ Wp, float* __restrict__ bp)
{
    int idx = blockIdx.x * blockDim.x + threadIdx.x;
    const int NW4 = HID * MPK / 4;
    if (idx < NW4) {
        int row = idx / (MPK / 4);
        int col = (idx % (MPK / 4)) * 4;
        int b   = col >> 9;
        int c   = col & 511;
        const float* srcs[5] = {w0, w1, w2, w3, w4};
        *(float4*)(Wp + (size_t)row * MPK + col) =
            *(const float4*)(srcs[b] + (size_t)row * HC + c);
    } else if (idx < NW4 + MPK) {
        int col = idx - NW4;
        int b = col >> 9, c = col & 511;
        float v = 0.f;
        if (b == 1) v = b1[c];
        else if (b == 2) v = b2[c];
        else if (b == 3) v = b3[c];
        else if (b == 4) v = b4[c];
        bp[col] = v;
    }
}

// ---------------------------------------------------------------------------
// CSR build (by dst)
// ---------------------------------------------------------------------------
__global__ void deg_count(const int* __restrict__ dst, int* __restrict__ deg)
{
    int e = blockIdx.x * blockDim.x + threadIdx.x;
    if (e < EE) atomicAdd(&deg[dst[e]], 1);
}

__global__ void scan_offsets(const int* __restrict__ deg,
                             int* __restrict__ off, int* __restrict__ cur)
{
    extern __shared__ int sdeg[];
    __shared__ int wsum[32];
    const int t    = threadIdx.x;
    const int lane = t & 31;
    const int wid  = t >> 5;
    const int CH   = (NN + 1023) / 1024;

    for (int i = t; i < NN; i += 1024) sdeg[i] = deg[i];
    __syncthreads();

    int base = t * CH;
    int s = 0;
#pragma unroll
    for (int i = 0; i < CH; i++) {
        int idx = base + i;
        if (idx < NN) s += sdeg[idx];
    }
    int v = s;
#pragma unroll
    for (int o = 1; o < 32; o <<= 1) {
        int u = __shfl_up_sync(0xffffffffu, v, o);
        if (lane >= o) v += u;
    }
    if (lane == 31) wsum[wid] = v;
    __syncthreads();
    if (wid == 0) {
        int w = wsum[lane];
#pragma unroll
        for (int o = 1; o < 32; o <<= 1) {
            int u = __shfl_up_sync(0xffffffffu, w, o);
            if (lane >= o) w += u;
        }
        wsum[lane] = w;
    }
    __syncthreads();
    int excl = v - s + (wid ? wsum[wid - 1] : 0);
#pragma unroll
    for (int i = 0; i < CH; i++) {
        int idx = base + i;
        if (idx < NN) {
            off[idx] = excl;
            cur[idx] = excl;
            excl += sdeg[idx];
        }
    }
    if (t == 1023) off[NN] = excl;
}

__global__ void build_srcs(const int* __restrict__ src, const int* __restrict__ dst,
                           int* __restrict__ cur, int* __restrict__ srcs)
{
    int e = blockIdx.x * blockDim.x + threadIdx.x;
    if (e >= EE) return;
    int pos = atomicAdd(&cur[dst[e]], 1);
    srcs[pos] = src[e];
}

// ---------------------------------------------------------------------------
// GraphConv aggregation via CSR
// ---------------------------------------------------------------------------
__global__ void gconv_agg(const float* __restrict__ in,
                          const int* __restrict__ off,
                          const int* __restrict__ srcs,
                          float* __restrict__ agg)
{
    int d = blockIdx.x;
    int c = threadIdx.x;
    int e0 = off[d], e1 = off[d + 1];
    float s = 0.f;
    int i = e0;
    for (; i + 3 < e1; i += 4) {
        int s0 = srcs[i], s1 = srcs[i + 1], s2 = srcs[i + 2], s3 = srcs[i + 3];
        s += in[(size_t)s0 * HID + c] + in[(size_t)s1 * HID + c]
           + in[(size_t)s2 * HID + c] + in[(size_t)s3 * HID + c];
    }
    for (; i < e1; ++i)
        s += in[(size_t)srcs[i] * HID + c];
    agg[(size_t)d * HID + c] = s;
}

// ---------------------------------------------------------------------------
// Attention + transformer epilogue fused, 8 warps/node (2 warps per head).
// q/k/v gathered from compact fp16 kvq buffer; ts/skip from fp32 pack.
// ---------------------------------------------------------------------------
__device__ __forceinline__ float4 ld_half4(const __half* p) {
    uint2 u = *(const uint2*)p;
    float2 fa = __half22float2(*(__half2*)&u.x);
    float2 fb = __half22float2(*(__half2*)&u.y);
    return make_float4(fa.x, fa.y, fb.x, fb.y);
}

__global__ void __launch_bounds__(256)
attn_fused(const float* __restrict__ pack,
           const __half* __restrict__ kvq,
           const int* __restrict__ off,
           const int* __restrict__ srcs,
           float* __restrict__ h2)
{
    __shared__ float s_m[4], s_den[4], s_acc[4][128];

    int d    = blockIdx.x;
    int w    = threadIdx.x >> 5;
    int lane = threadIdx.x & 31;
    int h    = w & 3;
    int half = w >> 2;
    int e0 = off[d], e1 = off[d + 1];
    int emid = (e0 + e1) >> 1;
    int lo = half ? emid : e0;
    int hi = half ? e1   : emid;

    const int kvbase = 512 + h * 256;     // k at +0, v at +128 (halves)

    float4 qv = ld_half4(kvq + (size_t)d * KVW + h * HID + lane * 4);
    float4 acc = make_float4(0.f, 0.f, 0.f, 0.f);
    float mrun = NEGBIG, den = 0.f;

    int i = lo;
    for (; i + 1 < hi; i += 2) {
        int s0 = srcs[i], s1 = srcs[i + 1];
        const __half* p0 = kvq + (size_t)s0 * KVW + kvbase + lane * 4;
        const __half* p1 = kvq + (size_t)s1 * KVW + kvbase + lane * 4;
        float4 k0 = ld_half4(p0);
        float4 k1 = ld_half4(p1);
        float4 v0 = ld_half4(p0 + 128);
        float4 v1 = ld_half4(p1 + 128);
        float d0 = qv.x * k0.x + qv.y * k0.y + qv.z * k0.z + qv.w * k0.w;
        float d1 = qv.x * k1.x + qv.y * k1.y + qv.z * k1.z + qv.w * k1.w;
#pragma unroll
        for (int o = 16; o; o >>= 1) {
            d0 += __shfl_xor_sync(0xffffffffu, d0, o);
            d1 += __shfl_xor_sync(0xffffffffu, d1, o);
        }
        d0 *= 0.08838834764831843f;
        d1 *= 0.08838834764831843f;

        float mnew = fmaxf(mrun, d0);
        float corr = __expf(mrun - mnew);
        float wt   = __expf(d0 - mnew);
        den = den * corr + wt;
        acc.x = acc.x * corr + wt * v0.x;
        acc.y = acc.y * corr + wt * v0.y;
        acc.z = acc.z * corr + wt * v0.z;
        acc.w = acc.w * corr + wt * v0.w;
        mrun = mnew;

        mnew = fmaxf(mrun, d1);
        corr = __expf(mrun - mnew);
        wt   = __expf(d1 - mnew);
        den = den * corr + wt;
        acc.x = acc.x * corr + wt * v1.x;
        acc.y = acc.y * corr + wt * v1.y;
        acc.z = acc.z * corr + wt * v1.z;
        acc.w = acc.w * corr + wt * v1.w;
        mrun = mnew;
    }
    if (i < hi) {
        int s0 = srcs[i];
        const __half* p0 = kvq + (size_t)s0 * KVW + kvbase + lane * 4;
        float4 k0 = ld_half4(p0);
        float4 v0 = ld_half4(p0 + 128);
        float d0 = qv.x * k0.x + qv.y * k0.y + qv.z * k0.z + qv.w * k0.w;
#pragma unroll
        for (int o = 16; o; o >>= 1) d0 += __shfl_xor_sync(0xffffffffu, d0, o);
        d0 *= 0.08838834764831843f;
        float mnew = fmaxf(mrun, d0);
        float corr = __expf(mrun - mnew);
        float wt   = __expf(d0 - mnew);
        den = den * corr + wt;
        acc.x = acc.x * corr + wt * v0.x;
        acc.y = acc.y * corr + wt * v0.y;
        acc.z = acc.z * corr + wt * v0.z;
        acc.w = acc.w * corr + wt * v0.w;
        mrun = mnew;
    }

    if (half == 1) {
        if (lane == 0) { s_m[h] = mrun; s_den[h] = den; }
        *((float4*)&s_acc[h][0] + lane) = acc;
    }
    __syncthreads();
    if (half == 0) {
        float m1 = s_m[h], den1 = s_den[h];
        float4 a1 = *((const float4*)&s_acc[h][0] + lane);
        float mnew = fmaxf(mrun, m1);
        float c0 = __expf(mrun - mnew);
        float c1 = __expf(m1 - mnew);
        den = den * c0 + den1 * c1;
        acc.x = acc.x * c0 + a1.x * c1;
        acc.y = acc.y * c0 + a1.y * c1;
        acc.z = acc.z * c0 + a1.z * c1;
        acc.w = acc.w * c0 + a1.w * c1;

        float inv = 1.f / (den + 1e-16f);
        float4 ts = *((const float4*)(pack + 2048 + (size_t)d * MPK + h * HID) + lane);
        float4 sk = *((const float4*)(pack + 0    + (size_t)d * MPK + h * HID) + lane);
        float4 r;
        r.x = fmaxf(acc.x * inv + ts.x + sk.x, 0.f);
        r.y = fmaxf(acc.y * inv + ts.y + sk.y, 0.f);
        r.z = fmaxf(acc.z * inv + ts.z + sk.z, 0.f);
        r.w = fmaxf(acc.w * inv + ts.w + sk.w, 0.f);
        *((float4*)(h2 + (size_t)d * HC + h * HID) + lane) = r;
    }
}

// ---------------------------------------------------------------------------
// Pooling (batch sorted: accumulate runs, flush atomics on group change)
// ---------------------------------------------------------------------------
#define PB 64
__global__ void pool_accum(const float* __restrict__ h,
                           const int* __restrict__ batch,
                           float* __restrict__ pool, float* __restrict__ cnt)
{
    int c  = threadIdx.x;
    int n0 = blockIdx.x * PB;
    int n1 = min(n0 + PB, NN);
    float s = 0.f;
    int cb = batch[n0], count = 0;
    for (int n = n0; n < n1; ++n) {
        int b = batch[n];
        if (b != cb) {
            atomicAdd(&pool[cb * HID + c], s);
            if (c == 0) atomicAdd(&cnt[cb], (float)count);
            s = 0.f; count = 0; cb = b;
        }
        s += h[(size_t)n * HID + c];
        count++;
    }
    atomicAdd(&pool[cb * HID + c], s);
    if (c == 0) atomicAdd(&cnt[cb], (float)count);
}

__global__ void pool_fc(const float* __restrict__ pool,
                        const float* __restrict__ cnt,
                        const float* __restrict__ fcW,
                        const float* __restrict__ fcb,
                        float* __restrict__ out)
{
    int g = blockIdx.x;
    int c = threadIdx.x;
    float inv = 1.f / fmaxf(cnt[g], 1.f);
    float s = 0.f;
    for (int k = 0; k < HID; k++)
        s += pool[g * HID + k] * fcW[k * NCC + c];
    out[g * NCC + c] = s * inv + fcb[c];
}

// ---------------------------------------------------------------------------
// Launch
// ---------------------------------------------------------------------------
extern "C" void kernel_launch(void* const* d_in, const int* in_sizes, int n_in,
                              void* d_out, int out_size)
{
    const float* x        = (const float*)d_in[0];
    const int*   ei       = (const int*)  d_in[1];
    const int*   src      = ei;
    const int*   dst      = ei + EE;
    const int*   batch    = (const int*)  d_in[2];
    const float* c1_Wr    = (const float*)d_in[3];
    const float* c1_br    = (const float*)d_in[4];
    const float* c1_Wroot = (const float*)d_in[5];
    const float* tq_W  = (const float*)d_in[6];  const float* tq_b  = (const float*)d_in[7];
    const float* tk_W  = (const float*)d_in[8];  const float* tk_b  = (const float*)d_in[9];
    const float* tv_W  = (const float*)d_in[10]; const float* tv_b  = (const float*)d_in[11];
    const float* ts_W  = (const float*)d_in[12]; const float* ts_b  = (const float*)d_in[13];
    const float* skip_W = (const float*)d_in[14];
    const float* l1W    = (const float*)d_in[15]; const float* l1b = (const float*)d_in[16];
    const float* g1_Wr = (const float*)d_in[17]; const float* g1_br = (const float*)d_in[18];
    const float* g1_Wroot = (const float*)d_in[19];
    const float* g2_Wr = (const float*)d_in[20]; const float* g2_br = (const float*)d_in[21];
    const float* g2_Wroot = (const float*)d_in[22];
    const float* fc_W = (const float*)d_in[23]; const float* fc_b = (const float*)d_in[24];
    float* out = (float*)d_out;

    float *agg, *h, *h3, *h4, *h5, *pack, *h2, *Wpk, *bpk, *pool, *cnt;
    __half* kvq;
    int *deg, *cur, *off, *srcs;
    cudaGetSymbolAddress((void**)&agg,  g_agg);
    cudaGetSymbolAddress((void**)&h,    g_h);
    cudaGetSymbolAddress((void**)&h3,   g_h3);
    cudaGetSymbolAddress((void**)&h4,   g_h4);
    cudaGetSymbolAddress((void**)&h5,   g_h5);
    cudaGetSymbolAddress((void**)&pack, g_pack);
    cudaGetSymbolAddress((void**)&kvq,  g_kvq);
    cudaGetSymbolAddress((void**)&h2,   g_h2);
    cudaGetSymbolAddress((void**)&Wpk,  g_Wpk);
    cudaGetSymbolAddress((void**)&bpk,  g_bpk);
    cudaGetSymbolAddress((void**)&pool, g_pool);
    cudaGetSymbolAddress((void**)&cnt,  g_cnt);
    cudaGetSymbolAddress((void**)&deg,  g_deg);
    cudaGetSymbolAddress((void**)&cur,  g_cur);
    cudaGetSymbolAddress((void**)&off,  g_off);
    cudaGetSymbolAddress((void**)&srcs, g_srcs);

    const int SCAN_SMEM = NN * (int)sizeof(int);
    cudaFuncSetAttribute(scan_offsets, cudaFuncAttributeMaxDynamicSharedMemorySize,
                         SCAN_SMEM);

    const dim3 gb(256);
    const dim3 grid128((NN + 127) / 128, 2);
    const dim3 gridPK ((NN + 127) / 128, MPK / 64);

    // --- weight+bias packing (independent)
    pack_wb<<<(HID * MPK / 4 + MPK + 255) / 256, 256>>>(
        skip_W, tq_W, tk_W, tv_W, ts_W, tq_b, tk_b, tv_b, ts_b, Wpk, bpk);

    // --- CSR build (by dst)
    cudaMemsetAsync(deg, 0, NN * sizeof(int));
    deg_count<<<(EE + 255) / 256, 256>>>(dst, deg);
    scan_offsets<<<1, 1024, SCAN_SMEM>>>(deg, off, cur);
    build_srcs<<<(EE + 255) / 256, 256>>>(src, dst, cur, srcs);

    // --- conv1: h = relu( (agg x) @ Wr + br + x @ Wroot )
    gconv_agg<<<NN, 128>>>(x, off, srcs, agg);
    gemm_mma<<<grid128, gb>>>(agg, c1_Wr, x, c1_Wroot, c1_br,
                              nullptr, h, nullptr, NN, 128, 128, 1);

    // --- packed projections: skip/ts -> fp32 pack, q/k/v -> fp16 kvq
    gemm_mma<<<gridPK, gb>>>(h, Wpk, nullptr, nullptr, bpk,
                             nullptr, pack, kvq, NN, 128, MPK, 0);

    // --- attention + fused epilogue
    attn_fused<<<NN, 256>>>(pack, kvq, off, srcs, h2);

    // --- h3 = relu(h2 @ lin1_W + lin1_b)
    gemm_mma<<<grid128, gb>>>(h2, l1W, nullptr, nullptr, l1b,
                              nullptr, h3, nullptr, NN, 512, 128, 1);

    // --- gconv l1 with residual
    gconv_agg<<<NN, 128>>>(h3, off, srcs, agg);
    gemm_mma<<<grid128, gb>>>(agg, g1_Wr, h3, g1_Wroot, g1_br,
                              h3, h4, nullptr, NN, 128, 128, 1);

    // --- gconv l2 with residual
    gconv_agg<<<NN, 128>>>(h4, off, srcs, agg);
    gemm_mma<<<grid128, gb>>>(agg, g2_Wr, h4, g2_Wroot, g2_br,
                              h4, h5, nullptr, NN, 128, 128, 1);

    // --- mean pool + fc
    cudaMemsetAsync(pool, 0, (size_t)GG * HID * sizeof(float));
    cudaMemsetAsync(cnt,  0, (size_t)GG * sizeof(float));
    pool_accum<<<(NN + PB - 1) / PB, 128>>>(h5, batch, pool, cnt);
    pool_fc<<<GG, NCC>>>(pool, cnt, fc_W, fc_b, out);
}